// round 11
// baseline (speedup 1.0000x reference)
#include <cuda_runtime.h>
#include <cstdint>

// Problem constants (fixed shapes from reference)
#define NUM_CLASSES 16
#define C_IN 21
#define D_HID 12      // 2*NUM_PARTS
#define P_OUT 7       // NUM_PARTS+1
#define BS 4
#define V 8
#define N_IMG (BS*V)  // 32
#define H 128
#define W 128
#define HW (H*W)      // 16384
#define EPS 1e-5f

#define PIX_PER_THREAD 8
#define THREADS 128
#define PIX_PER_BLOCK (THREADS * PIX_PER_THREAD)        // 1024
#define BLOCKS_PER_IMG (HW / PIX_PER_BLOCK)             // 16
#define GRID (N_IMG * BLOCKS_PER_IMG)                   // 512

// Output layout: tuple (out, feats) flattened:
//   out:   (32, 7, 128, 128)  at offset 0
//   feats: (32, 21, 128, 128) after it
#define OUT_ELEMS ((size_t)N_IMG * P_OUT * HW)

typedef unsigned long long u64;

// ---- packed f32x2 helpers (Blackwell FFMA2; ptxas never auto-fuses) ----
__device__ __forceinline__ u64 pack2(float a, float b) {
    u64 r;
    asm("mov.b64 %0, {%1, %2};" : "=l"(r) : "f"(a), "f"(b));
    return r;
}
__device__ __forceinline__ void unpack2(u64 v, float& a, float& b) {
    asm("mov.b64 {%0, %1}, %2;" : "=f"(a), "=f"(b) : "l"(v));
}
__device__ __forceinline__ u64 fma2(u64 a, u64 b, u64 c) {
    u64 d;
    asm("fma.rn.f32x2 %0, %1, %2, %3;" : "=l"(d) : "l"(a), "l"(b), "l"(c));
    return d;
}

// ---- 256-bit global accesses (sm_100+/sm_103a: ld/st.global.v8.b32) ----
__device__ __forceinline__ void ldg256(const float* p, uint32_t r[8]) {
    asm volatile("ld.global.v8.b32 {%0,%1,%2,%3,%4,%5,%6,%7}, [%8];"
                 : "=r"(r[0]), "=r"(r[1]), "=r"(r[2]), "=r"(r[3]),
                   "=r"(r[4]), "=r"(r[5]), "=r"(r[6]), "=r"(r[7])
                 : "l"(p));
}
__device__ __forceinline__ void stg256_cs(float* p, const uint32_t r[8]) {
    asm volatile("st.global.cs.v8.b32 [%0], {%1,%2,%3,%4,%5,%6,%7,%8};"
                 :: "l"(p),
                    "r"(r[0]), "r"(r[1]), "r"(r[2]), "r"(r[3]),
                    "r"(r[4]), "r"(r[5]), "r"(r[6]), "r"(r[7])
                 : "memory");
}

__global__ __launch_bounds__(THREADS, 4)   // 128-reg ceiling for the 96-reg acc block
void mvpartseg_v8_kernel(const float* __restrict__ x,     // (32,21,128,128)
                         const int*   __restrict__ cls,   // (4,1)
                         const float* __restrict__ W1,    // (16,12,21)
                         const float* __restrict__ b1,    // (16,12)
                         const float* __restrict__ g1,    // (16,12)
                         const float* __restrict__ be1,   // (16,12)
                         const float* __restrict__ rm1,   // (16,12)
                         const float* __restrict__ rv1,   // (16,12)
                         const float* __restrict__ W2,    // (16,7,12)
                         const float* __restrict__ b2,    // (16,7)
                         float* __restrict__ out)
{
    __shared__ __align__(16) float sA1t[C_IN * D_HID];   // [c][d], BN-folded
    __shared__ __align__(16) float sA2[P_OUT * D_HID];   // [p][d]
    __shared__ float sc1[D_HID];
    __shared__ float sb2[P_OUT];
    __shared__ float sinv[D_HID];

    const int t = threadIdx.x;
    const int n = blockIdx.x / BLOCKS_PER_IMG;       // image (view-folded) index
    const int k = cls[n / V];                        // selected class head

    // Fold BN into conv1 params
    if (t < D_HID) {
        const int i = k * D_HID + t;
        float inv = g1[i] * rsqrtf(rv1[i] + EPS);
        sinv[t] = inv;
        sc1[t]  = b1[i] * inv + be1[i] - rm1[i] * inv;
    }
    if (t < P_OUT) sb2[t] = b2[k * P_OUT + t];
    __syncthreads();

    for (int i = t; i < C_IN * D_HID; i += THREADS) {
        int c = i / D_HID, d = i % D_HID;
        sA1t[i] = W1[k * D_HID * C_IN + d * C_IN + c] * sinv[d];
    }
    for (int i = t; i < P_OUT * D_HID; i += THREADS) {
        sA2[i] = W2[k * P_OUT * D_HID + i];
    }
    __syncthreads();

    const int pix = (blockIdx.x % BLOCKS_PER_IMG) * PIX_PER_BLOCK + t * PIX_PER_THREAD;
    const float* xin  = x + (size_t)n * C_IN * HW + pix;       // 32B-aligned
    float*       fout = out + OUT_ELEMS + (size_t)n * C_IN * HW + pix;

    // Layer-1 accumulators: 8 pixels = 4 packed f32x2 lanes per hidden unit
    u64 acc[D_HID][4];
#pragma unroll
    for (int d = 0; d < D_HID; d++) {
        u64 bp = pack2(sc1[d], sc1[d]);
#pragma unroll
        for (int g = 0; g < 4; g++) acc[d][g] = bp;
    }

    // Stream channels: 1 LDG.256 + 1 STG.256 (feats) + 48 fma2 per channel.
#pragma unroll
    for (int c = 0; c < C_IN; c++) {
        uint32_t r[8];
        ldg256(xin + (size_t)c * HW, r);
        stg256_cs(fout + (size_t)c * HW, r);
        u64 xg[4];
#pragma unroll
        for (int g = 0; g < 4; g++)
            xg[g] = pack2(__uint_as_float(r[2 * g]), __uint_as_float(r[2 * g + 1]));
        const float4* wrow = (const float4*)&sA1t[c * D_HID];
#pragma unroll
        for (int q = 0; q < D_HID / 4; q++) {
            const float4 w = wrow[q];
            const u64 w0 = pack2(w.x, w.x);
            const u64 w1 = pack2(w.y, w.y);
            const u64 w2 = pack2(w.z, w.z);
            const u64 w3 = pack2(w.w, w.w);
#pragma unroll
            for (int g = 0; g < 4; g++) {
                acc[4*q+0][g] = fma2(w0, xg[g], acc[4*q+0][g]);
                acc[4*q+1][g] = fma2(w1, xg[g], acc[4*q+1][g]);
                acc[4*q+2][g] = fma2(w2, xg[g], acc[4*q+2][g]);
                acc[4*q+3][g] = fma2(w3, xg[g], acc[4*q+3][g]);
            }
        }
    }

    // ReLU hidden (packed, in place)
#pragma unroll
    for (int d = 0; d < D_HID; d++) {
#pragma unroll
        for (int g = 0; g < 4; g++) {
            float a, b;
            unpack2(acc[d][g], a, b);
            acc[d][g] = pack2(fmaxf(a, 0.0f), fmaxf(b, 0.0f));
        }
    }

    // Layer 2 (packed) + final relu; STG.256 per output channel.
    float* oout = out + (size_t)n * P_OUT * HW + pix;
#pragma unroll
    for (int p = 0; p < P_OUT; p++) {
        const float bb = sb2[p];
        u64 o[4];
        const u64 bp = pack2(bb, bb);
#pragma unroll
        for (int g = 0; g < 4; g++) o[g] = bp;
#pragma unroll
        for (int d = 0; d < D_HID; d++) {
            const float wv = sA2[p * D_HID + d];
            const u64 wq = pack2(wv, wv);
#pragma unroll
            for (int g = 0; g < 4; g++) o[g] = fma2(wq, acc[d][g], o[g]);
        }
        uint32_t r[8];
#pragma unroll
        for (int g = 0; g < 4; g++) {
            float a, b;
            unpack2(o[g], a, b);
            r[2 * g]     = __float_as_uint(fmaxf(a, 0.0f));
            r[2 * g + 1] = __float_as_uint(fmaxf(b, 0.0f));
        }
        stg256_cs(oout + (size_t)p * HW, r);
    }
}

extern "C" void kernel_launch(void* const* d_in, const int* in_sizes, int n_in,
                              void* d_out, int out_size)
{
    const float* x   = (const float*)d_in[0];
    const int*   cls = (const int*)  d_in[1];
    const float* W1  = (const float*)d_in[2];
    const float* b1  = (const float*)d_in[3];
    const float* g1  = (const float*)d_in[4];
    const float* be1 = (const float*)d_in[5];
    const float* rm1 = (const float*)d_in[6];
    const float* rv1 = (const float*)d_in[7];
    const float* W2  = (const float*)d_in[8];
    const float* b2  = (const float*)d_in[9];
    float* out = (float*)d_out;

    mvpartseg_v8_kernel<<<GRID, THREADS>>>(x, cls, W1, b1, g1, be1, rm1, rv1,
                                           W2, b2, out);
}

// round 12
// speedup vs baseline: 1.1012x; 1.1012x over previous
#include <cuda_runtime.h>
#include <cstdint>

// Problem constants (fixed shapes from reference)
#define NUM_CLASSES 16
#define C_IN 21
#define D_HID 12      // 2*NUM_PARTS
#define P_OUT 7       // NUM_PARTS+1
#define BS 4
#define V 8
#define N_IMG (BS*V)  // 32
#define H 128
#define W 128
#define HW (H*W)      // 16384
#define EPS 1e-5f

#define PIX_PER_THREAD 4
#define THREADS 128
#define PIX_PER_BLOCK (THREADS * PIX_PER_THREAD)        // 512
#define BLOCKS_PER_IMG (HW / PIX_PER_BLOCK)             // 32
#define GRID_COMPUTE (N_IMG * BLOCKS_PER_IMG)           // 1024
#define GRID_COPY 344                                   // feats memcpy blocks
#define GRID (GRID_COMPUTE + GRID_COPY)                 // 1368

// Output layout: tuple (out, feats) flattened:
//   out:   (32, 7, 128, 128)  at offset 0
//   feats: (32, 21, 128, 128) after it
#define OUT_ELEMS ((size_t)N_IMG * P_OUT * HW)
#define FEATS_ELEMS ((size_t)N_IMG * C_IN * HW)         // 11,010,048 floats
#define FEATS_VEC4 (FEATS_ELEMS / 4)                    // 2,752,512 float4

typedef unsigned long long u64;

// ---- packed f32x2 helpers (Blackwell FFMA2; ptxas never auto-fuses) ----
__device__ __forceinline__ u64 pack2(float a, float b) {
    u64 r;
    asm("mov.b64 %0, {%1, %2};" : "=l"(r) : "f"(a), "f"(b));
    return r;
}
__device__ __forceinline__ void unpack2(u64 v, float& a, float& b) {
    asm("mov.b64 {%0, %1}, %2;" : "=f"(a), "=f"(b) : "l"(v));
}
__device__ __forceinline__ u64 fma2(u64 a, u64 b, u64 c) {
    u64 d;
    asm("fma.rn.f32x2 %0, %1, %2, %3;" : "=l"(d) : "l"(a), "l"(b), "l"(c));
    return d;
}

__global__ __launch_bounds__(THREADS, 6)
void mvpartseg_split_kernel(const float* __restrict__ x,     // (32,21,128,128)
                            const int*   __restrict__ cls,   // (4,1)
                            const float* __restrict__ W1,    // (16,12,21)
                            const float* __restrict__ b1,    // (16,12)
                            const float* __restrict__ g1,    // (16,12)
                            const float* __restrict__ be1,   // (16,12)
                            const float* __restrict__ rm1,   // (16,12)
                            const float* __restrict__ rv1,   // (16,12)
                            const float* __restrict__ W2,    // (16,7,12)
                            const float* __restrict__ b2,    // (16,7)
                            float* __restrict__ out)
{
    const int t = threadIdx.x;

    // ================= COPY personality: feats = x (pure streaming) ========
    if (blockIdx.x >= GRID_COMPUTE) {
        const int cb = blockIdx.x - GRID_COMPUTE;
        const float4* src = (const float4*)x;
        float4* dst = (float4*)(out + OUT_ELEMS);
        // grid-stride over 2,752,512 float4; 344 blocks * 128 thr = 44032 lanes
        const int stride = GRID_COPY * THREADS;
        for (int i = cb * THREADS + t; i < FEATS_VEC4; i += stride) {
            __stcs(&dst[i], __ldg(&src[i]));
        }
        return;
    }

    // ================= COMPUTE personality (round-5 path, no feats) ========
    __shared__ __align__(16) float sA1t[C_IN * D_HID];   // [c][d], BN-folded
    __shared__ __align__(16) float sA2[P_OUT * D_HID];   // [p][d]
    __shared__ float sc1[D_HID];
    __shared__ float sb2[P_OUT];
    __shared__ float sinv[D_HID];

    const int n = blockIdx.x / BLOCKS_PER_IMG;       // image (view-folded) index
    const int k = cls[n / V];                        // selected class head

    // Fold BN into conv1 params
    if (t < D_HID) {
        const int i = k * D_HID + t;
        float inv = g1[i] * rsqrtf(rv1[i] + EPS);
        sinv[t] = inv;
        sc1[t]  = b1[i] * inv + be1[i] - rm1[i] * inv;
    }
    if (t < P_OUT) sb2[t] = b2[k * P_OUT + t];
    __syncthreads();

    for (int i = t; i < C_IN * D_HID; i += THREADS) {
        int c = i / D_HID, d = i % D_HID;
        sA1t[i] = W1[k * D_HID * C_IN + d * C_IN + c] * sinv[d];
    }
    for (int i = t; i < P_OUT * D_HID; i += THREADS) {
        sA2[i] = W2[k * P_OUT * D_HID + i];
    }
    __syncthreads();

    const int pix = (blockIdx.x % BLOCKS_PER_IMG) * PIX_PER_BLOCK + t * PIX_PER_THREAD;
    const float* xin = x + (size_t)n * C_IN * HW + pix;

    // Layer-1 accumulators: 4 pixels = 2 packed f32x2 lanes per hidden unit
    u64 acc01[D_HID], acc23[D_HID];
#pragma unroll
    for (int d = 0; d < D_HID; d++) {
        u64 bp = pack2(sc1[d], sc1[d]);
        acc01[d] = bp;
        acc23[d] = bp;
    }

    // Stream channels: LDG.128 -> packed FFMA2 into accumulators.
#pragma unroll
    for (int c = 0; c < C_IN; c++) {
        const float4 xv = *(const float4*)(xin + (size_t)c * HW);
        const u64 x01 = pack2(xv.x, xv.y);
        const u64 x23 = pack2(xv.z, xv.w);
        const float4* wrow = (const float4*)&sA1t[c * D_HID];
#pragma unroll
        for (int q = 0; q < D_HID / 4; q++) {
            const float4 w = wrow[q];
            const u64 w0 = pack2(w.x, w.x);
            const u64 w1 = pack2(w.y, w.y);
            const u64 w2 = pack2(w.z, w.z);
            const u64 w3 = pack2(w.w, w.w);
            acc01[4*q+0] = fma2(w0, x01, acc01[4*q+0]);
            acc23[4*q+0] = fma2(w0, x23, acc23[4*q+0]);
            acc01[4*q+1] = fma2(w1, x01, acc01[4*q+1]);
            acc23[4*q+1] = fma2(w1, x23, acc23[4*q+1]);
            acc01[4*q+2] = fma2(w2, x01, acc01[4*q+2]);
            acc23[4*q+2] = fma2(w2, x23, acc23[4*q+2]);
            acc01[4*q+3] = fma2(w3, x01, acc01[4*q+3]);
            acc23[4*q+3] = fma2(w3, x23, acc23[4*q+3]);
        }
    }

    // Unpack + ReLU hidden -> scalar float4 per hidden unit
    float4 hv[D_HID];
#pragma unroll
    for (int d = 0; d < D_HID; d++) {
        float a, b, cc, dd;
        unpack2(acc01[d], a, b);
        unpack2(acc23[d], cc, dd);
        hv[d] = make_float4(fmaxf(a, 0.0f), fmaxf(b, 0.0f),
                            fmaxf(cc, 0.0f), fmaxf(dd, 0.0f));
    }

    // Layer 2 + final relu (max over masked classes == relu of selected head)
    const size_t out_base = (size_t)n * P_OUT * HW + pix;
#pragma unroll
    for (int p = 0; p < P_OUT; p++) {
        float bb = sb2[p];
        float4 o = make_float4(bb, bb, bb, bb);
#pragma unroll
        for (int d = 0; d < D_HID; d++) {
            const float w = sA2[p * D_HID + d];
            o.x = fmaf(w, hv[d].x, o.x);
            o.y = fmaf(w, hv[d].y, o.y);
            o.z = fmaf(w, hv[d].z, o.z);
            o.w = fmaf(w, hv[d].w, o.w);
        }
        o.x = fmaxf(o.x, 0.0f);
        o.y = fmaxf(o.y, 0.0f);
        o.z = fmaxf(o.z, 0.0f);
        o.w = fmaxf(o.w, 0.0f);
        __stcs((float4*)(out + out_base + (size_t)p * HW), o);
    }
}

extern "C" void kernel_launch(void* const* d_in, const int* in_sizes, int n_in,
                              void* d_out, int out_size)
{
    const float* x   = (const float*)d_in[0];
    const int*   cls = (const int*)  d_in[1];
    const float* W1  = (const float*)d_in[2];
    const float* b1  = (const float*)d_in[3];
    const float* g1  = (const float*)d_in[4];
    const float* be1 = (const float*)d_in[5];
    const float* rm1 = (const float*)d_in[6];
    const float* rv1 = (const float*)d_in[7];
    const float* W2  = (const float*)d_in[8];
    const float* b2  = (const float*)d_in[9];
    float* out = (float*)d_out;

    mvpartseg_split_kernel<<<GRID, THREADS>>>(x, cls, W1, b1, g1, be1, rm1, rv1,
                                              W2, b2, out);
}

// round 14
// speedup vs baseline: 1.3626x; 1.2374x over previous
#include <cuda_runtime.h>
#include <cstdint>

// Problem constants (fixed shapes from reference)
#define NUM_CLASSES 16
#define C_IN 21
#define D_HID 12      // 2*NUM_PARTS
#define P_OUT 7       // NUM_PARTS+1
#define BS 4
#define V 8
#define N_IMG (BS*V)  // 32
#define H 128
#define W 128
#define HW (H*W)      // 16384
#define EPS 1e-5f

#define PIX_PER_THREAD 4
#define THREADS 128
#define PIX_PER_BLOCK (THREADS * PIX_PER_THREAD)        // 512
#define BLOCKS_PER_IMG (HW / PIX_PER_BLOCK)             // 32
#define GRID (N_IMG * BLOCKS_PER_IMG)                   // 1024

// Output layout: tuple (out, feats) flattened:
//   out:   (32, 7, 128, 128)  at offset 0
//   feats: (32, 21, 128, 128) after it
#define OUT_ELEMS ((size_t)N_IMG * P_OUT * HW)

typedef unsigned long long u64;

// ---- packed f32x2 helpers (Blackwell FFMA2; ptxas never auto-fuses) ----
__device__ __forceinline__ u64 pack2(float a, float b) {
    u64 r;
    asm("mov.b64 %0, {%1, %2};" : "=l"(r) : "f"(a), "f"(b));
    return r;
}
__device__ __forceinline__ void unpack2(u64 v, float& a, float& b) {
    asm("mov.b64 {%0, %1}, %2;" : "=f"(a), "=f"(b) : "l"(v));
}
__device__ __forceinline__ u64 fma2(u64 a, u64 b, u64 c) {
    u64 d;
    asm("fma.rn.f32x2 %0, %1, %2, %3;" : "=l"(d) : "l"(a), "l"(b), "l"(c));
    return d;
}

__global__ __launch_bounds__(THREADS, 6)
void mvpartseg_fused_kernel(const float* __restrict__ x,     // (32,21,128,128)
                            const int*   __restrict__ cls,   // (4,1)
                            const float* __restrict__ W1,    // (16,12,21)
                            const float* __restrict__ b1,    // (16,12)
                            const float* __restrict__ g1,    // (16,12)
                            const float* __restrict__ be1,   // (16,12)
                            const float* __restrict__ rm1,   // (16,12)
                            const float* __restrict__ rv1,   // (16,12)
                            const float* __restrict__ W2,    // (16,7,12)
                            const float* __restrict__ b2,    // (16,7)
                            float* __restrict__ out)
{
    // Layer-1 weights [c][d] (d contiguous): adjacent d-pairs form the f32x2
    // weight operand directly -- NO register duplication movs needed.
    __shared__ __align__(16) float sA1t[C_IN * D_HID];   // 252, BN-folded
    __shared__ __align__(16) float sA2[P_OUT * D_HID];   // 84, [p][d]
    __shared__ float sc1[D_HID];
    __shared__ float sb2[P_OUT];
    __shared__ float sinv[D_HID];

    const int t = threadIdx.x;
    const int n = blockIdx.x / BLOCKS_PER_IMG;       // image (view-folded) index
    const int k = cls[n / V];                        // selected class head

    // Fold BN into conv1 params
    if (t < D_HID) {
        const int i = k * D_HID + t;
        float inv = g1[i] * rsqrtf(rv1[i] + EPS);
        sinv[t] = inv;
        sc1[t]  = b1[i] * inv + be1[i] - rm1[i] * inv;
    }
    if (t < P_OUT) sb2[t] = b2[k * P_OUT + t];
    __syncthreads();

    for (int i = t; i < C_IN * D_HID; i += THREADS) {
        int c = i / D_HID, d = i % D_HID;
        sA1t[i] = W1[k * D_HID * C_IN + d * C_IN + c] * sinv[d];
    }
    for (int i = t; i < P_OUT * D_HID; i += THREADS) {
        sA2[i] = W2[k * P_OUT * D_HID + i];
    }
    __syncthreads();

    const int pix = (blockIdx.x % BLOCKS_PER_IMG) * PIX_PER_BLOCK + t * PIX_PER_THREAD;
    const float* xin  = x + (size_t)n * C_IN * HW + pix;
    float*       fout = out + OUT_ELEMS + (size_t)n * C_IN * HW + pix;

    // Accumulators: acc[px][dd] = packed (h[2dd], h[2dd+1]) for pixel px.
    // 4 px * 6 pairs = 24 u64 = 48 regs.
    u64 acc[PIX_PER_THREAD][D_HID / 2];
#pragma unroll
    for (int dd = 0; dd < D_HID / 2; dd++) {
        const u64 bp = pack2(sc1[2 * dd], sc1[2 * dd + 1]);
#pragma unroll
        for (int p = 0; p < PIX_PER_THREAD; p++) acc[p][dd] = bp;
    }

    // Stream channels: LDG.128, STG.128 feats, then per channel:
    // 3 LDS.128 of packed weight pairs + 4 pixel-dup movs + 24 fma2.
#pragma unroll
    for (int c = 0; c < C_IN; c++) {
        const float4 xv = __ldg((const float4*)(xin + (size_t)c * HW));
        __stcs((float4*)(fout + (size_t)c * HW), xv);
        u64 xd[PIX_PER_THREAD];
        xd[0] = pack2(xv.x, xv.x);
        xd[1] = pack2(xv.y, xv.y);
        xd[2] = pack2(xv.z, xv.z);
        xd[3] = pack2(xv.w, xv.w);
        const ulonglong2* wrow = (const ulonglong2*)&sA1t[c * D_HID];
        const ulonglong2 wA = wrow[0];   // pairs (d0,d1),(d2,d3)
        const ulonglong2 wB = wrow[1];   // pairs (d4,d5),(d6,d7)
        const ulonglong2 wC = wrow[2];   // pairs (d8,d9),(d10,d11)
#pragma unroll
        for (int p = 0; p < PIX_PER_THREAD; p++) {
            acc[p][0] = fma2(wA.x, xd[p], acc[p][0]);
            acc[p][1] = fma2(wA.y, xd[p], acc[p][1]);
            acc[p][2] = fma2(wB.x, xd[p], acc[p][2]);
            acc[p][3] = fma2(wB.y, xd[p], acc[p][3]);
            acc[p][4] = fma2(wC.x, xd[p], acc[p][4]);
            acc[p][5] = fma2(wC.y, xd[p], acc[p][5]);
        }
    }

    // ReLU hidden (packed over d-pairs, in place)
#pragma unroll
    for (int p = 0; p < PIX_PER_THREAD; p++) {
#pragma unroll
        for (int dd = 0; dd < D_HID / 2; dd++) {
            float a, b;
            unpack2(acc[p][dd], a, b);
            acc[p][dd] = pack2(fmaxf(a, 0.0f), fmaxf(b, 0.0f));
        }
    }

    // Layer 2: packed partial sums over d-pairs, horizontal add per output.
    // (max over masked classes == relu of the selected head)
    const size_t out_base = (size_t)n * P_OUT * HW + pix;
#pragma unroll
    for (int po = 0; po < P_OUT; po++) {
        const ulonglong2* wrow = (const ulonglong2*)&sA2[po * D_HID];
        const ulonglong2 wA = wrow[0];
        const ulonglong2 wB = wrow[1];
        const ulonglong2 wC = wrow[2];
        const float bb = sb2[po];
        float res[PIX_PER_THREAD];
#pragma unroll
        for (int p = 0; p < PIX_PER_THREAD; p++) {
            u64 o = fma2(wA.x, acc[p][0], (u64)0);  // 0.0f pair
            o = fma2(wA.y, acc[p][1], o);
            o = fma2(wB.x, acc[p][2], o);
            o = fma2(wB.y, acc[p][3], o);
            o = fma2(wC.x, acc[p][4], o);
            o = fma2(wC.y, acc[p][5], o);
            float a, b;
            unpack2(o, a, b);
            res[p] = fmaxf(a + b + bb, 0.0f);
        }
        __stcs((float4*)(out + out_base + (size_t)po * HW),
               make_float4(res[0], res[1], res[2], res[3]));
    }
}

extern "C" void kernel_launch(void* const* d_in, const int* in_sizes, int n_in,
                              void* d_out, int out_size)
{
    const float* x   = (const float*)d_in[0];
    const int*   cls = (const int*)  d_in[1];
    const float* W1  = (const float*)d_in[2];
    const float* b1  = (const float*)d_in[3];
    const float* g1  = (const float*)d_in[4];
    const float* be1 = (const float*)d_in[5];
    const float* rm1 = (const float*)d_in[6];
    const float* rv1 = (const float*)d_in[7];
    const float* W2  = (const float*)d_in[8];
    const float* b2  = (const float*)d_in[9];
    float* out = (float*)d_out;

    mvpartseg_fused_kernel<<<GRID, THREADS>>>(x, cls, W1, b1, g1, be1, rm1, rv1,
                                              W2, b2, out);
}